// round 2
// baseline (speedup 1.0000x reference)
#include <cuda_runtime.h>

#define L1LEN 512
#define L2LEN 512
#define DDIM  256
#define BATCH 2
#define NG    16   // groups (softmax per group)
#define GS    16   // group size
#define TI    8    // target rows per block
#define TJ    64   // source rows per tile
#define NTILE (L2LEN / TJ)
#define SCSTR 20   // padded inner stride for score tile [TI][TJ][SCSTR]
#define KSTR  260  // padded row stride for K/V tiles (floats)

__device__ float g_Q[BATCH * L1LEN * DDIM];
__device__ float g_K[BATCH * L2LEN * DDIM];
__device__ float g_V[BATCH * L2LEN * DDIM];

// ---------------------------------------------------------------------------
// QKV projection: y[m][e] = sum_d x[m][d] * W[e][d]   (M=1024, N=256, K=256)
// blockIdx.z selects Q (x_target,Wq) / K (x_source,Wk) / V (x_source,Wv).
// 64x64 tile, BK=16, 256 threads, 4x4 micro-tile per thread.
// ---------------------------------------------------------------------------
__global__ __launch_bounds__(256) void qkv_gemm(const float* __restrict__ x_target,
                                                const float* __restrict__ x_source,
                                                const float* __restrict__ Wq,
                                                const float* __restrict__ Wk,
                                                const float* __restrict__ Wv) {
    const int z = blockIdx.z;
    const float* __restrict__ x = (z == 0) ? x_target : x_source;
    const float* __restrict__ W = (z == 0) ? Wq : ((z == 1) ? Wk : Wv);
    float* __restrict__ y       = (z == 0) ? g_Q : ((z == 1) ? g_K : g_V);

    __shared__ float xsh[16][68];
    __shared__ float wsh[16][68];

    const int t  = threadIdx.x;
    const int tx = t & 15;        // micro col group
    const int ty = t >> 4;        // micro row group
    const int m_blk = blockIdx.x * 64;
    const int n_blk = blockIdx.y * 64;

    const int lr = t >> 2;        // 0..63 : tile row being loaded
    const int lc = (t & 3) * 4;   // 0,4,8,12 : k-offset quad

    float c[4][4] = {};

    for (int k0 = 0; k0 < DDIM; k0 += 16) {
        float4 xv = *(const float4*)&x[(m_blk + lr) * DDIM + k0 + lc];
        float4 wv = *(const float4*)&W[(n_blk + lr) * DDIM + k0 + lc];
        __syncthreads();
        xsh[lc + 0][lr] = xv.x; xsh[lc + 1][lr] = xv.y;
        xsh[lc + 2][lr] = xv.z; xsh[lc + 3][lr] = xv.w;
        wsh[lc + 0][lr] = wv.x; wsh[lc + 1][lr] = wv.y;
        wsh[lc + 2][lr] = wv.z; wsh[lc + 3][lr] = wv.w;
        __syncthreads();
#pragma unroll
        for (int kk = 0; kk < 16; kk++) {
            float4 a = *(const float4*)&xsh[kk][ty * 4];
            float4 bq = *(const float4*)&wsh[kk][tx * 4];
            float av[4] = {a.x, a.y, a.z, a.w};
            float bv[4] = {bq.x, bq.y, bq.z, bq.w};
#pragma unroll
            for (int r = 0; r < 4; r++)
#pragma unroll
                for (int cc = 0; cc < 4; cc++)
                    c[r][cc] += av[r] * bv[cc];
        }
    }

#pragma unroll
    for (int r = 0; r < 4; r++) {
        float4 o = make_float4(c[r][0], c[r][1], c[r][2], c[r][3]);
        *(float4*)&y[(m_blk + ty * 4 + r) * DDIM + n_blk + tx * 4] = o;
    }
}

// ---------------------------------------------------------------------------
// Fused grouped-vector attention with online softmax.
// Grid: BATCH * (L1/TI) = 128 blocks, 256 threads.
// Per tile: load K/V tile -> scores -> online softmax update -> accumulate out.
// ---------------------------------------------------------------------------
__global__ __launch_bounds__(256, 1) void attn_kernel(const float* __restrict__ wmlp,
                                                      const float* __restrict__ bmlp,
                                                      float* __restrict__ out) {
    extern __shared__ float sm[];
    float* q   = sm;                      // TI * DDIM                = 2048
    float* kt  = q + TI * DDIM;           // TJ * KSTR                = 16640
    float* vt  = kt + TJ * KSTR;          // TJ * KSTR                = 16640
    float* sc  = vt + TJ * KSTR;          // TI * TJ * SCSTR          = 10240
    float* msh = sc + TI * TJ * SCSTR;    // TI * NG                  = 128
    float* lsh = msh + TI * NG;           // 128
    float* ssh = lsh + TI * NG;           // 128 (rescale factors)

    const int t      = threadIdx.x;
    const int b      = blockIdx.x >> 6;           // /(L1/TI)
    const int itile  = blockIdx.x & 63;
    const int i_base = itile * TI;

    const int warp = t >> 5;
    const int lane = t & 31;
    const int n0   = (4 * lane) & 15;             // group quad base for phase D

    const int i0 = t >> 6;                        // phase-B row (and i0+4)
    const int jj = t & 63;                        // phase-B col

    // MLP weights in registers
    float w[GS];
#pragma unroll
    for (int g = 0; g < GS; g++) w[g] = wmlp[g];
    const float b0 = bmlp[0];

    // load Q rows for this block
    {
        const float* Qg = g_Q + (b * L1LEN + i_base) * DDIM;
        for (int idx = t; idx < TI * DDIM / 4; idx += 256) {
            int row = idx >> 6, col = (idx & 63) * 4;
            *(float4*)&q[row * DDIM + col] = *(const float4*)&Qg[row * DDIM + col];
        }
    }
    if (t < TI * NG) { msh[t] = 0.f; lsh[t] = 0.f; }

    float acc0[4] = {0.f, 0.f, 0.f, 0.f};
    float acc1[4] = {0.f, 0.f, 0.f, 0.f};

    for (int tile = 0; tile < NTILE; tile++) {
        __syncthreads();  // protect kt/vt/sc from previous phase D readers

        // -------- Phase A: stage K/V tile into shared (coalesced float4)
        {
            const float* Kg = g_K + (b * L2LEN + tile * TJ) * DDIM;
            const float* Vg = g_V + (b * L2LEN + tile * TJ) * DDIM;
            for (int idx = t; idx < TJ * (DDIM / 4); idx += 256) {
                int row = idx >> 6, col = (idx & 63) * 4;
                *(float4*)&kt[row * KSTR + col] = *(const float4*)&Kg[row * DDIM + col];
                *(float4*)&vt[row * KSTR + col] = *(const float4*)&Vg[row * DDIM + col];
            }
        }
        __syncthreads();

        // -------- Phase B: scores for (i0,jj) and (i0+4,jj)
        {
            const float* qa = q + i0 * DDIM;
            const float* qb = q + (i0 + 4) * DDIM;
            const float* kr = kt + jj * KSTR;
            float* sra = sc + (i0 * TJ + jj) * SCSTR;
            float* srb = sc + ((i0 + 4) * TJ + jj) * SCSTR;
#pragma unroll 4
            for (int n = 0; n < NG; n++) {
                float s0 = 0.f, s1 = 0.f;
#pragma unroll
                for (int dq = 0; dq < 4; dq++) {
                    const int d = n * GS + dq * 4;
                    float4 kv = *(const float4*)&kr[d];
                    float4 q0 = *(const float4*)&qa[d];
                    float4 q1 = *(const float4*)&qb[d];
                    s0 += fmaxf(q0.x - kv.x, 0.f) * w[dq * 4 + 0];
                    s0 += fmaxf(q0.y - kv.y, 0.f) * w[dq * 4 + 1];
                    s0 += fmaxf(q0.z - kv.z, 0.f) * w[dq * 4 + 2];
                    s0 += fmaxf(q0.w - kv.w, 0.f) * w[dq * 4 + 3];
                    s1 += fmaxf(q1.x - kv.x, 0.f) * w[dq * 4 + 0];
                    s1 += fmaxf(q1.y - kv.y, 0.f) * w[dq * 4 + 1];
                    s1 += fmaxf(q1.z - kv.z, 0.f) * w[dq * 4 + 2];
                    s1 += fmaxf(q1.w - kv.w, 0.f) * w[dq * 4 + 3];
                }
                sra[n] = fmaxf(s0 + b0, 0.f);
                srb[n] = fmaxf(s1 + b0, 0.f);
            }
        }
        __syncthreads();

        // -------- Phase C: online softmax update, one thread per (i,n)
        if (t < TI * NG) {
            const int ci = t >> 4, cn = t & 15;
            float* base = sc + ci * TJ * SCSTR + cn;
            float mo = msh[t];
            float mt = mo;
#pragma unroll 8
            for (int j = 0; j < TJ; j++) mt = fmaxf(mt, base[j * SCSTR]);
            float corr = __expf(mo - mt);
            float sum = 0.f;
#pragma unroll 8
            for (int j = 0; j < TJ; j++) {
                float e = __expf(base[j * SCSTR] - mt);
                base[j * SCSTR] = e;
                sum += e;
            }
            lsh[t] = lsh[t] * corr + sum;
            msh[t] = mt;
            ssh[t] = corr;
        }
        __syncthreads();

        // -------- Phase D: accumulate output (thread = (i=warp, two d-quads))
        {
            const int i = warp;
            float4 cr = *(const float4*)&ssh[i * NG + n0];
            acc0[0] *= cr.x; acc0[1] *= cr.y; acc0[2] *= cr.z; acc0[3] *= cr.w;
            acc1[0] *= cr.x; acc1[1] *= cr.y; acc1[2] *= cr.z; acc1[3] *= cr.w;
            const float* scb = sc + i * TJ * SCSTR + n0;
#pragma unroll 4
            for (int j = 0; j < TJ; j++) {
                float4 p  = *(const float4*)&scb[j * SCSTR];
                float4 v0 = *(const float4*)&vt[j * KSTR + 4 * lane];
                float4 v1 = *(const float4*)&vt[j * KSTR + 4 * lane + 128];
                acc0[0] += p.x * v0.x; acc0[1] += p.y * v0.y;
                acc0[2] += p.z * v0.z; acc0[3] += p.w * v0.w;
                acc1[0] += p.x * v1.x; acc1[1] += p.y * v1.y;
                acc1[2] += p.z * v1.z; acc1[3] += p.w * v1.w;
            }
        }
    }

    // -------- finalize: normalize and write
    {
        const int i = warp;
        float4 lv = *(const float4*)&lsh[i * NG + n0];
        float4 r0 = make_float4(acc0[0] / lv.x, acc0[1] / lv.y,
                                acc0[2] / lv.z, acc0[3] / lv.w);
        float4 r1 = make_float4(acc1[0] / lv.x, acc1[1] / lv.y,
                                acc1[2] / lv.z, acc1[3] / lv.w);
        float* orow = out + (b * L1LEN + i_base + i) * DDIM;
        *(float4*)&orow[4 * lane]       = r0;
        *(float4*)&orow[4 * lane + 128] = r1;
    }
}

// ---------------------------------------------------------------------------
extern "C" void kernel_launch(void* const* d_in, const int* in_sizes, int n_in,
                              void* d_out, int out_size) {
    const float* x_source = (const float*)d_in[0];  // (B, L2, D)
    const float* x_target = (const float*)d_in[1];  // (B, L1, D)
    const float* Wq       = (const float*)d_in[2];
    const float* Wk       = (const float*)d_in[3];
    const float* Wv       = (const float*)d_in[4];
    const float* w_mlp    = (const float*)d_in[5];
    const float* b_mlp    = (const float*)d_in[6];
    float* out            = (float*)d_out;

    // QKV projections
    dim3 ggrid(16, 4, 3);
    qkv_gemm<<<ggrid, 256>>>(x_target, x_source, Wq, Wk, Wv);

    // fused attention
    const size_t smem_bytes =
        (TI * DDIM + 2 * TJ * KSTR + TI * TJ * SCSTR + 3 * TI * NG) * sizeof(float);
    cudaFuncSetAttribute(attn_kernel, cudaFuncAttributeMaxDynamicSharedMemorySize,
                         (int)smem_bytes);
    attn_kernel<<<BATCH * (L1LEN / TI), 256, smem_bytes>>>(w_mlp, b_mlp, out);
}

// round 4
// speedup vs baseline: 1.1653x; 1.1653x over previous
#include <cuda_runtime.h>

#define L1LEN 512
#define L2LEN 512
#define DDIM  256
#define BATCH 2
#define NG    16
#define GS    16
#define TI    8
#define TJ    64
#define NTILE (L2LEN / TJ)
#define KSTR  260          // padded K/V row stride (floats)
#define JS    68           // sc1 row stride (floats), multiple of 4
#define NSTR  20           // sc2 inner stride
#define NTHR  512

__device__ float g_Q[BATCH * L1LEN * DDIM];
__device__ float g_K[BATCH * L2LEN * DDIM];
__device__ float g_V[BATCH * L2LEN * DDIM];

// ---------------------------------------------------------------------------
// QKV projection: y[m][e] = sum_d x[m][d] * W[e][d]   (M=1024, N=256, K=256)
// ---------------------------------------------------------------------------
__global__ __launch_bounds__(256) void qkv_gemm(const float* __restrict__ x_target,
                                                const float* __restrict__ x_source,
                                                const float* __restrict__ Wq,
                                                const float* __restrict__ Wk,
                                                const float* __restrict__ Wv) {
    const int z = blockIdx.z;
    const float* __restrict__ x = (z == 0) ? x_target : x_source;
    const float* __restrict__ W = (z == 0) ? Wq : ((z == 1) ? Wk : Wv);
    float* __restrict__ y       = (z == 0) ? g_Q : ((z == 1) ? g_K : g_V);

    __shared__ float xsh[16][68];
    __shared__ float wsh[16][68];

    const int t  = threadIdx.x;
    const int tx = t & 15;
    const int ty = t >> 4;
    const int m_blk = blockIdx.x * 64;
    const int n_blk = blockIdx.y * 64;
    const int lr = t >> 2;
    const int lc = (t & 3) * 4;

    float c[4][4] = {};

    for (int k0 = 0; k0 < DDIM; k0 += 16) {
        float4 xv = *(const float4*)&x[(m_blk + lr) * DDIM + k0 + lc];
        float4 wv = *(const float4*)&W[(n_blk + lr) * DDIM + k0 + lc];
        __syncthreads();
        xsh[lc + 0][lr] = xv.x; xsh[lc + 1][lr] = xv.y;
        xsh[lc + 2][lr] = xv.z; xsh[lc + 3][lr] = xv.w;
        wsh[lc + 0][lr] = wv.x; wsh[lc + 1][lr] = wv.y;
        wsh[lc + 2][lr] = wv.z; wsh[lc + 3][lr] = wv.w;
        __syncthreads();
#pragma unroll
        for (int kk = 0; kk < 16; kk++) {
            float4 a  = *(const float4*)&xsh[kk][ty * 4];
            float4 bq = *(const float4*)&wsh[kk][tx * 4];
            float av[4] = {a.x, a.y, a.z, a.w};
            float bv[4] = {bq.x, bq.y, bq.z, bq.w};
#pragma unroll
            for (int r = 0; r < 4; r++)
#pragma unroll
                for (int cc = 0; cc < 4; cc++)
                    c[r][cc] += av[r] * bv[cc];
        }
    }

#pragma unroll
    for (int r = 0; r < 4; r++) {
        float4 o = make_float4(c[r][0], c[r][1], c[r][2], c[r][3]);
        *(float4*)&y[(m_blk + ty * 4 + r) * DDIM + n_blk + tx * 4] = o;
    }
}

// ---------------------------------------------------------------------------
// Fused grouped-vector attention, 512 threads, 16 warps.
//   B: thread (jj, nc) computes scores for all 8 i, 2 groups -> sc1[i][n][j]
//   C: thread (i,n) row-softmax (float4), exp -> sc2[i][j][n]
//   D: thread (qp, ip, jh): RI=2 i-rows x RD=8 dims, j-split 4-way
// ---------------------------------------------------------------------------
__global__ __launch_bounds__(NTHR, 1) void attn_kernel(const float* __restrict__ wmlp,
                                                       const float* __restrict__ bmlp,
                                                       float* __restrict__ out) {
    extern __shared__ float sm[];
    float* q   = sm;                        // 2048
    float* kt  = q + TI * DDIM;             // 16640
    float* vt  = kt + TJ * KSTR;            // 16640
    float* sc1 = vt + TJ * KSTR;            // 128*68 = 8704  [(i*16+n)*JS + j]
    float* sc2 = sc1 + TI * NG * JS;        // 8*64*20 = 10240 [(i*64+j)*NSTR + n]
    float* msh = sc2 + TI * TJ * NSTR;      // 128
    float* lsh = msh + TI * NG;             // 128
    float* ssh = lsh + TI * NG;             // 128

    const int t      = threadIdx.x;
    const int b      = blockIdx.x >> 6;
    const int itile  = blockIdx.x & 63;
    const int i_base = itile * TI;

    // phase B ids
    const int jj = t & 63;
    const int nc = t >> 6;                  // 0..7 -> groups 2nc, 2nc+1
    // phase D ids
    const int qp = t & 31;                  // d-quad: d = 4qp and 4qp+128
    const int ip = (t >> 5) & 3;            // i rows: ip, ip+4
    const int jh = t >> 7;                  // j-split 0..3
    const int n0 = (4 * qp) & 15;

    float w[GS];
#pragma unroll
    for (int g = 0; g < GS; g++) w[g] = wmlp[g];
    const float b0 = bmlp[0];

    // load Q block (one float4 per thread)
    {
        const float* Qg = g_Q + (b * L1LEN + i_base) * DDIM;
        int row = t >> 6, col = (t & 63) * 4;
        *(float4*)&q[row * DDIM + col] = *(const float4*)&Qg[row * DDIM + col];
    }
    if (t < TI * NG) { msh[t] = 0.f; lsh[t] = 0.f; }

    float acc[2][2][4] = {};   // [i-row (ip / ip+4)][quad (d / d+128)][component]

    for (int tile = 0; tile < NTILE; tile++) {
        __syncthreads();
        // ---- Phase A: stage K/V tiles
        {
            const float* Kg = g_K + (b * L2LEN + tile * TJ) * DDIM;
            const float* Vg = g_V + (b * L2LEN + tile * TJ) * DDIM;
#pragma unroll
            for (int it = 0; it < (TJ * DDIM / 4) / NTHR; it++) {
                int idx = t + it * NTHR;
                int row = idx >> 6, col = (idx & 63) * 4;
                *(float4*)&kt[row * KSTR + col] = *(const float4*)&Kg[row * DDIM + col];
                *(float4*)&vt[row * KSTR + col] = *(const float4*)&Vg[row * DDIM + col];
            }
        }
        __syncthreads();

        // ---- Phase B: scores; K read once, Q via warp broadcast
        {
            const float* kr = kt + jj * KSTR;
            float s[8][2];
#pragma unroll
            for (int i = 0; i < 8; i++) { s[i][0] = 0.f; s[i][1] = 0.f; }
#pragma unroll
            for (int n2 = 0; n2 < 2; n2++) {
                const int n = nc * 2 + n2;
#pragma unroll
                for (int dq = 0; dq < 4; dq++) {
                    const int d = n * GS + dq * 4;
                    float4 kv = *(const float4*)&kr[d];
                    const float w0 = w[dq * 4 + 0], w1 = w[dq * 4 + 1];
                    const float w2 = w[dq * 4 + 2], w3 = w[dq * 4 + 3];
#pragma unroll
                    for (int i = 0; i < 8; i++) {
                        float4 qv = *(const float4*)&q[i * DDIM + d];
                        s[i][n2] += fmaxf(qv.x - kv.x, 0.f) * w0
                                  + fmaxf(qv.y - kv.y, 0.f) * w1
                                  + fmaxf(qv.z - kv.z, 0.f) * w2
                                  + fmaxf(qv.w - kv.w, 0.f) * w3;
                    }
                }
            }
#pragma unroll
            for (int i = 0; i < 8; i++) {
#pragma unroll
                for (int n2 = 0; n2 < 2; n2++) {
                    sc1[(i * NG + nc * 2 + n2) * JS + jj] =
                        fmaxf(s[i][n2] + b0, 0.f);
                }
            }
        }
        __syncthreads();

        // ---- Phase C: row softmax (online), exp -> sc2
        if (t < TI * NG) {
            const int ci = t >> 4, cn = t & 15;
            const float* row = sc1 + t * JS;
            float mo = msh[t], mt = mo;
#pragma unroll
            for (int jq = 0; jq < TJ / 4; jq++) {
                float4 v = *(const float4*)&row[jq * 4];
                mt = fmaxf(mt, fmaxf(fmaxf(v.x, v.y), fmaxf(v.z, v.w)));
            }
            float corr = __expf(mo - mt);
            float sum = 0.f;
            float* dst = sc2 + ci * TJ * NSTR + cn;
#pragma unroll
            for (int jq = 0; jq < TJ / 4; jq++) {
                float4 v = *(const float4*)&row[jq * 4];
                float e0 = __expf(v.x - mt), e1 = __expf(v.y - mt);
                float e2 = __expf(v.z - mt), e3 = __expf(v.w - mt);
                sum += (e0 + e1) + (e2 + e3);
                dst[(jq * 4 + 0) * NSTR] = e0;
                dst[(jq * 4 + 1) * NSTR] = e1;
                dst[(jq * 4 + 2) * NSTR] = e2;
                dst[(jq * 4 + 3) * NSTR] = e3;
            }
            lsh[t] = lsh[t] * corr + sum;
            msh[t] = mt;
            ssh[t] = corr;
        }
        __syncthreads();

        // ---- Phase D: accumulate; 2 i-rows, 8 dims, quarter of j per thread
        {
            float4 c0 = *(const float4*)&ssh[ip * NG + n0];
            float4 c1 = *(const float4*)&ssh[(ip + 4) * NG + n0];
            acc[0][0][0] *= c0.x; acc[0][0][1] *= c0.y; acc[0][0][2] *= c0.z; acc[0][0][3] *= c0.w;
            acc[0][1][0] *= c0.x; acc[0][1][1] *= c0.y; acc[0][1][2] *= c0.z; acc[0][1][3] *= c0.w;
            acc[1][0][0] *= c1.x; acc[1][0][1] *= c1.y; acc[1][0][2] *= c1.z; acc[1][0][3] *= c1.w;
            acc[1][1][0] *= c1.x; acc[1][1][1] *= c1.y; acc[1][1][2] *= c1.z; acc[1][1][3] *= c1.w;
            const int j0 = jh * (TJ / 4);
#pragma unroll 4
            for (int jo = 0; jo < TJ / 4; jo++) {
                const int j = j0 + jo;
                float4 p0 = *(const float4*)&sc2[(ip * TJ + j) * NSTR + n0];
                float4 p1 = *(const float4*)&sc2[((ip + 4) * TJ + j) * NSTR + n0];
                float4 v0 = *(const float4*)&vt[j * KSTR + 4 * qp];
                float4 v1 = *(const float4*)&vt[j * KSTR + 4 * qp + 128];
                acc[0][0][0] += p0.x * v0.x; acc[0][0][1] += p0.y * v0.y;
                acc[0][0][2] += p0.z * v0.z; acc[0][0][3] += p0.w * v0.w;
                acc[0][1][0] += p0.x * v1.x; acc[0][1][1] += p0.y * v1.y;
                acc[0][1][2] += p0.z * v1.z; acc[0][1][3] += p0.w * v1.w;
                acc[1][0][0] += p1.x * v0.x; acc[1][0][1] += p1.y * v0.y;
                acc[1][0][2] += p1.z * v0.z; acc[1][0][3] += p1.w * v0.w;
                acc[1][1][0] += p1.x * v1.x; acc[1][1][1] += p1.y * v1.y;
                acc[1][1][2] += p1.z * v1.z; acc[1][1][3] += p1.w * v1.w;
            }
        }
    }

    // ---- merge j-splits and write out
    __syncthreads();
    {
        float* scr = sc1;  // reuse: 4 splits * 128 slots * 16 floats = 8192
        int base = jh * 2048 + (ip * 32 + qp) * 16;
        *(float4*)&scr[base + 0]  = *(float4*)&acc[0][0][0];
        *(float4*)&scr[base + 4]  = *(float4*)&acc[0][1][0];
        *(float4*)&scr[base + 8]  = *(float4*)&acc[1][0][0];
        *(float4*)&scr[base + 12] = *(float4*)&acc[1][1][0];
    }
    __syncthreads();
    if (t < 128) {
        const int slot = t;
        const int mip = slot >> 5, mqp = slot & 31;
        const int mn0 = (4 * mqp) & 15;
        float* scr = sc1;
        float r[16];
#pragma unroll
        for (int e = 0; e < 16; e += 4) {
            float4 a0 = *(float4*)&scr[0    + slot * 16 + e];
            float4 a1 = *(float4*)&scr[2048 + slot * 16 + e];
            float4 a2 = *(float4*)&scr[4096 + slot * 16 + e];
            float4 a3 = *(float4*)&scr[6144 + slot * 16 + e];
            r[e + 0] = a0.x + a1.x + a2.x + a3.x;
            r[e + 1] = a0.y + a1.y + a2.y + a3.y;
            r[e + 2] = a0.z + a1.z + a2.z + a3.z;
            r[e + 3] = a0.w + a1.w + a2.w + a3.w;
        }
        float4 l0 = *(const float4*)&lsh[mip * NG + mn0];
        float4 l1 = *(const float4*)&lsh[(mip + 4) * NG + mn0];
        float* o0 = out + (b * L1LEN + i_base + mip) * DDIM;
        float* o1 = out + (b * L1LEN + i_base + mip + 4) * DDIM;
        *(float4*)&o0[4 * mqp] =
            make_float4(r[0] / l0.x, r[1] / l0.y, r[2] / l0.z, r[3] / l0.w);
        *(float4*)&o0[4 * mqp + 128] =
            make_float4(r[4] / l0.x, r[5] / l0.y, r[6] / l0.z, r[7] / l0.w);
        *(float4*)&o1[4 * mqp] =
            make_float4(r[8] / l1.x, r[9] / l1.y, r[10] / l1.z, r[11] / l1.w);
        *(float4*)&o1[4 * mqp + 128] =
            make_float4(r[12] / l1.x, r[13] / l1.y, r[14] / l1.z, r[15] / l1.w);
    }
}

// ---------------------------------------------------------------------------
extern "C" void kernel_launch(void* const* d_in, const int* in_sizes, int n_in,
                              void* d_out, int out_size) {
    const float* x_source = (const float*)d_in[0];
    const float* x_target = (const float*)d_in[1];
    const float* Wq       = (const float*)d_in[2];
    const float* Wk       = (const float*)d_in[3];
    const float* Wv       = (const float*)d_in[4];
    const float* w_mlp    = (const float*)d_in[5];
    const float* b_mlp    = (const float*)d_in[6];
    float* out            = (float*)d_out;

    dim3 ggrid(16, 4, 3);
    qkv_gemm<<<ggrid, 256>>>(x_target, x_source, Wq, Wk, Wv);

    const size_t smem_bytes =
        (TI * DDIM + 2 * TJ * KSTR + TI * NG * JS + TI * TJ * NSTR + 3 * TI * NG)
        * sizeof(float);
    cudaFuncSetAttribute(attn_kernel, cudaFuncAttributeMaxDynamicSharedMemorySize,
                         (int)smem_bytes);
    attn_kernel<<<BATCH * (L1LEN / TI), NTHR, smem_bytes>>>(w_mlp, b_mlp, out);
}

// round 5
// speedup vs baseline: 1.2801x; 1.0986x over previous
#include <cuda_runtime.h>

#define L1LEN 512
#define L2LEN 512
#define DDIM  256
#define BATCH 2
#define NG    16
#define GS    16
#define TI    8
#define TJ    32           // source rows per tile
#define NHALF 8            // tiles per CTA (256 j per CTA half)
#define KSTR  260          // padded K/V row stride (floats)
#define NSTR  20           // sc2 inner stride
#define NTHR  256

__device__ float g_Q[BATCH * L1LEN * DDIM];
__device__ float g_K[BATCH * L2LEN * DDIM];
__device__ float g_V[BATCH * L2LEN * DDIM];
__device__ float g_pacc[BATCH * 64 * 2 * TI * DDIM];   // partial outputs
__device__ float g_pl[BATCH * 64 * 2 * TI * NG];       // partial exp-sums

// ---------------------------------------------------------------------------
// QKV projection: y[m][e] = sum_d x[m][d] * W[e][d]   (M=1024, N=256, K=256)
// ---------------------------------------------------------------------------
__global__ __launch_bounds__(256) void qkv_gemm(const float* __restrict__ x_target,
                                                const float* __restrict__ x_source,
                                                const float* __restrict__ Wq,
                                                const float* __restrict__ Wk,
                                                const float* __restrict__ Wv) {
    const int z = blockIdx.z;
    const float* __restrict__ x = (z == 0) ? x_target : x_source;
    const float* __restrict__ W = (z == 0) ? Wq : ((z == 1) ? Wk : Wv);
    float* __restrict__ y       = (z == 0) ? g_Q : ((z == 1) ? g_K : g_V);

    __shared__ float xsh[16][68];
    __shared__ float wsh[16][68];

    const int t  = threadIdx.x;
    const int tx = t & 15;
    const int ty = t >> 4;
    const int m_blk = blockIdx.x * 64;
    const int n_blk = blockIdx.y * 64;
    const int lr = t >> 2;
    const int lc = (t & 3) * 4;

    float c[4][4] = {};

    for (int k0 = 0; k0 < DDIM; k0 += 16) {
        float4 xv = *(const float4*)&x[(m_blk + lr) * DDIM + k0 + lc];
        float4 wv = *(const float4*)&W[(n_blk + lr) * DDIM + k0 + lc];
        __syncthreads();
        xsh[lc + 0][lr] = xv.x; xsh[lc + 1][lr] = xv.y;
        xsh[lc + 2][lr] = xv.z; xsh[lc + 3][lr] = xv.w;
        wsh[lc + 0][lr] = wv.x; wsh[lc + 1][lr] = wv.y;
        wsh[lc + 2][lr] = wv.z; wsh[lc + 3][lr] = wv.w;
        __syncthreads();
#pragma unroll
        for (int kk = 0; kk < 16; kk++) {
            float4 a  = *(const float4*)&xsh[kk][ty * 4];
            float4 bq = *(const float4*)&wsh[kk][tx * 4];
            float av[4] = {a.x, a.y, a.z, a.w};
            float bv[4] = {bq.x, bq.y, bq.z, bq.w};
#pragma unroll
            for (int r = 0; r < 4; r++)
#pragma unroll
                for (int cc = 0; cc < 4; cc++)
                    c[r][cc] += av[r] * bv[cc];
        }
    }

#pragma unroll
    for (int r = 0; r < 4; r++) {
        float4 o = make_float4(c[r][0], c[r][1], c[r][2], c[r][3]);
        *(float4*)&y[(m_blk + ty * 4 + r) * DDIM + n_blk + tx * 4] = o;
    }
}

// ---------------------------------------------------------------------------
// Fused attention, j-split across 2 CTAs, no-max softmax (scores bounded).
// 256 threads, 2 CTAs/SM. Grid 256 = BATCH * 64 * 2.
//   B: thread (jj in 32, nc in 8): scores for 8 i x 2 groups, exp -> sc2
//   sum: t<128 accumulates sum_j exp (concurrent with D)
//   D: thread (qp,ip,jh): 2 i-rows x 8 dims x 16 j, unnormalized accumulate
// ---------------------------------------------------------------------------
__global__ __launch_bounds__(NTHR, 2) void attn_kernel(const float* __restrict__ wmlp,
                                                       const float* __restrict__ bmlp) {
    extern __shared__ float sm[];
    float* q   = sm;                        // 2048
    float* kt  = q + TI * DDIM;             // 32*260 = 8320
    float* vt  = kt + TJ * KSTR;            // 8320
    float* sc2 = vt + TJ * KSTR;            // 8*32*20 = 5120  [(i*TJ+j)*NSTR + n]

    const int t     = threadIdx.x;
    const int bx    = blockIdx.x;
    const int b     = bx >> 7;
    const int itile = (bx >> 1) & 63;
    const int jh2   = bx & 1;               // j half: 0 -> [0,256), 1 -> [256,512)
    const int i_base = itile * TI;
    const int part   = bx;                  // partial slot

    // phase B ids
    const int jj = t & 31;
    const int nc = t >> 5;                  // 0..7 -> groups 2nc, 2nc+1
    // phase D ids
    const int qp = t & 31;                  // d-quad: d = 4qp and 4qp+128
    const int ip = (t >> 5) & 3;            // i rows: ip, ip+4
    const int jh = t >> 7;                  // j-split 0..1 (16 j each)
    const int n0 = (4 * qp) & 15;

    float w[GS];
#pragma unroll
    for (int g = 0; g < GS; g++) w[g] = wmlp[g];
    const float b0 = bmlp[0];

    // load Q block
    {
        const float* Qg = g_Q + (b * L1LEN + i_base) * DDIM;
#pragma unroll
        for (int it = 0; it < 2; it++) {
            int idx = t + it * NTHR;
            int row = idx >> 6, col = (idx & 63) * 4;
            *(float4*)&q[row * DDIM + col] = *(const float4*)&Qg[row * DDIM + col];
        }
    }

    float acc[2][2][4] = {};
    float lsum = 0.f;                       // valid on t<128: (i=t>>4, n=t&15)

    for (int tile = 0; tile < NHALF; tile++) {
        __syncthreads();
        const int j_glob = jh2 * (L2LEN / 2) + tile * TJ;
        // ---- Phase A: stage K/V tiles
        {
            const float* Kg = g_K + (b * L2LEN + j_glob) * DDIM;
            const float* Vg = g_V + (b * L2LEN + j_glob) * DDIM;
#pragma unroll
            for (int it = 0; it < (TJ * DDIM / 4) / NTHR; it++) {
                int idx = t + it * NTHR;
                int row = idx >> 6, col = (idx & 63) * 4;
                *(float4*)&kt[row * KSTR + col] = *(const float4*)&Kg[row * DDIM + col];
                *(float4*)&vt[row * KSTR + col] = *(const float4*)&Vg[row * DDIM + col];
            }
        }
        __syncthreads();

        // ---- Phase B: scores + exp -> sc2 (K read once, Q broadcast)
        {
            const float* kr = kt + jj * KSTR;
            float s[8][2];
#pragma unroll
            for (int i = 0; i < 8; i++) { s[i][0] = 0.f; s[i][1] = 0.f; }
#pragma unroll
            for (int n2 = 0; n2 < 2; n2++) {
                const int n = nc * 2 + n2;
#pragma unroll
                for (int dq = 0; dq < 4; dq++) {
                    const int d = n * GS + dq * 4;
                    float4 kv = *(const float4*)&kr[d];
                    const float w0 = w[dq * 4 + 0], w1 = w[dq * 4 + 1];
                    const float w2 = w[dq * 4 + 2], w3 = w[dq * 4 + 3];
#pragma unroll
                    for (int i = 0; i < 8; i++) {
                        float4 qv = *(const float4*)&q[i * DDIM + d];
                        s[i][n2] += fmaxf(qv.x - kv.x, 0.f) * w0
                                  + fmaxf(qv.y - kv.y, 0.f) * w1
                                  + fmaxf(qv.z - kv.z, 0.f) * w2
                                  + fmaxf(qv.w - kv.w, 0.f) * w3;
                    }
                }
            }
#pragma unroll
            for (int i = 0; i < 8; i++) {
#pragma unroll
                for (int n2 = 0; n2 < 2; n2++) {
                    sc2[(i * TJ + jj) * NSTR + nc * 2 + n2] =
                        __expf(fmaxf(s[i][n2] + b0, 0.f));
                }
            }
        }
        __syncthreads();

        // ---- exp-sum (t<128, concurrent with D; no barrier between them)
        if (t < TI * NG) {
            const int ci = t >> 4, cn = t & 15;
            const float* base = sc2 + ci * TJ * NSTR + cn;
            float s0 = 0.f, s1 = 0.f;
#pragma unroll
            for (int j = 0; j < TJ; j += 2) {
                s0 += base[j * NSTR];
                s1 += base[(j + 1) * NSTR];
            }
            lsum += s0 + s1;
        }

        // ---- Phase D: unnormalized accumulate
        {
            const int j0 = jh * (TJ / 2);
#pragma unroll 4
            for (int jo = 0; jo < TJ / 2; jo++) {
                const int j = j0 + jo;
                float4 p0 = *(const float4*)&sc2[(ip * TJ + j) * NSTR + n0];
                float4 p1 = *(const float4*)&sc2[((ip + 4) * TJ + j) * NSTR + n0];
                float4 v0 = *(const float4*)&vt[j * KSTR + 4 * qp];
                float4 v1 = *(const float4*)&vt[j * KSTR + 4 * qp + 128];
                acc[0][0][0] += p0.x * v0.x; acc[0][0][1] += p0.y * v0.y;
                acc[0][0][2] += p0.z * v0.z; acc[0][0][3] += p0.w * v0.w;
                acc[0][1][0] += p0.x * v1.x; acc[0][1][1] += p0.y * v1.y;
                acc[0][1][2] += p0.z * v1.z; acc[0][1][3] += p0.w * v1.w;
                acc[1][0][0] += p1.x * v0.x; acc[1][0][1] += p1.y * v0.y;
                acc[1][0][2] += p1.z * v0.z; acc[1][0][3] += p1.w * v0.w;
                acc[1][1][0] += p1.x * v1.x; acc[1][1][1] += p1.y * v1.y;
                acc[1][1][2] += p1.z * v1.z; acc[1][1][3] += p1.w * v1.w;
            }
        }
    }

    // ---- merge jh halves in smem, write partials to global scratch
    __syncthreads();
    if (jh == 1) {
        float* scr = sc2;  // reuse: 128 slots * 16 floats
        int base = (ip * 32 + qp) * 16;
        *(float4*)&scr[base + 0]  = *(float4*)&acc[0][0][0];
        *(float4*)&scr[base + 4]  = *(float4*)&acc[0][1][0];
        *(float4*)&scr[base + 8]  = *(float4*)&acc[1][0][0];
        *(float4*)&scr[base + 12] = *(float4*)&acc[1][1][0];
    }
    __syncthreads();
    if (jh == 0) {
        float* scr = sc2;
        int base = (ip * 32 + qp) * 16;
        float4 a00 = *(float4*)&scr[base + 0];
        float4 a01 = *(float4*)&scr[base + 4];
        float4 a10 = *(float4*)&scr[base + 8];
        float4 a11 = *(float4*)&scr[base + 12];
        float* pb = g_pacc + part * (TI * DDIM);
        *(float4*)&pb[ip * DDIM + 4 * qp] =
            make_float4(acc[0][0][0] + a00.x, acc[0][0][1] + a00.y,
                        acc[0][0][2] + a00.z, acc[0][0][3] + a00.w);
        *(float4*)&pb[ip * DDIM + 4 * qp + 128] =
            make_float4(acc[0][1][0] + a01.x, acc[0][1][1] + a01.y,
                        acc[0][1][2] + a01.z, acc[0][1][3] + a01.w);
        *(float4*)&pb[(ip + 4) * DDIM + 4 * qp] =
            make_float4(acc[1][0][0] + a10.x, acc[1][0][1] + a10.y,
                        acc[1][0][2] + a10.z, acc[1][0][3] + a10.w);
        *(float4*)&pb[(ip + 4) * DDIM + 4 * qp + 128] =
            make_float4(acc[1][1][0] + a11.x, acc[1][1][1] + a11.y,
                        acc[1][1][2] + a11.z, acc[1][1][3] + a11.w);
    }
    if (t < TI * NG) g_pl[part * (TI * NG) + t] = lsum;
}

// ---------------------------------------------------------------------------
// Merge: out = (acc_half0 + acc_half1) / (l_half0 + l_half1)
// Grid 128 = BATCH*64, 256 threads; each thread 2 float4s.
// ---------------------------------------------------------------------------
__global__ __launch_bounds__(256) void merge_kernel(float* __restrict__ out) {
    const int bx = blockIdx.x;              // (b*64 + itile)
    const int t  = threadIdx.x;
    const int p0 = bx * 2, p1 = bx * 2 + 1;
    const float* a0 = g_pacc + p0 * (TI * DDIM);
    const float* a1 = g_pacc + p1 * (TI * DDIM);
    const float* l0 = g_pl + p0 * (TI * NG);
    const float* l1 = g_pl + p1 * (TI * NG);
    float* ob = out + bx * (TI * DDIM);

#pragma unroll
    for (int k = 0; k < 2; k++) {
        int idx = t + k * 256;              // 0..511 float4 slots
        int i   = idx >> 6;
        int d0  = (idx & 63) * 4;
        int n0  = d0 & 15;
        float4 x0 = *(const float4*)&a0[i * DDIM + d0];
        float4 x1 = *(const float4*)&a1[i * DDIM + d0];
        float4 u0 = *(const float4*)&l0[i * NG + n0];
        float4 u1 = *(const float4*)&l1[i * NG + n0];
        float4 r;
        r.x = (x0.x + x1.x) / (u0.x + u1.x);
        r.y = (x0.y + x1.y) / (u0.y + u1.y);
        r.z = (x0.z + x1.z) / (u0.z + u1.z);
        r.w = (x0.w + x1.w) / (u0.w + u1.w);
        *(float4*)&ob[i * DDIM + d0] = r;
    }
}

// ---------------------------------------------------------------------------
extern "C" void kernel_launch(void* const* d_in, const int* in_sizes, int n_in,
                              void* d_out, int out_size) {
    const float* x_source = (const float*)d_in[0];
    const float* x_target = (const float*)d_in[1];
    const float* Wq       = (const float*)d_in[2];
    const float* Wk       = (const float*)d_in[3];
    const float* Wv       = (const float*)d_in[4];
    const float* w_mlp    = (const float*)d_in[5];
    const float* b_mlp    = (const float*)d_in[6];
    float* out            = (float*)d_out;

    dim3 ggrid(16, 4, 3);
    qkv_gemm<<<ggrid, 256>>>(x_target, x_source, Wq, Wk, Wv);

    const size_t smem_bytes =
        (TI * DDIM + 2 * TJ * KSTR + TI * TJ * NSTR) * sizeof(float);
    cudaFuncSetAttribute(attn_kernel, cudaFuncAttributeMaxDynamicSharedMemorySize,
                         (int)smem_bytes);
    attn_kernel<<<BATCH * 64 * 2, NTHR, smem_bytes>>>(w_mlp, b_mlp);

    merge_kernel<<<BATCH * 64, 256>>>(out);
}